// round 5
// baseline (speedup 1.0000x reference)
#include <cuda_runtime.h>
#include <mma.h>
#include <cstdint>

using namespace nvcuda;

#define N_IMG 64
#define C_IN  64
#define H_IN  56
#define W_IN  56
#define K_OUT 128
#define H_OUT 54
#define W_OUT 54
#define PQ    (H_OUT * W_OUT)          /* 2916   */
#define NPQ   (N_IMG * PQ)             /* 186624 */

#define M_TILE 128
#define NCTA   (NPQ / M_TILE)          /* 1458 exact */
#define NTAPS  9

#define LDA 80                          /* A smem row stride, bytes (mult 16) */
#define LDB 80                          /* B smem col stride, bytes           */
#define LDO 132                         /* epilogue staging stride, floats    */

#define A_BYTES (128 * LDA)             /* 10240 */
#define B_BYTES (2 * 128 * LDB)         /* 20480 (two weight levels) */
#define STAGE   (A_BYTES + B_BYTES)     /* 30720 */
#define OFF_A   2048
#define SMEM_TOTAL (OFF_A + 128 * LDO * 4)   /* 2048 + 67584 = 69632 (> 2*STAGE) */

/* x as NHWC int8 (exact), weights prepacked [tap][lvl][ko][c] int8 */
__device__ signed char g_x8[(size_t)N_IMG * H_IN * W_IN * C_IN];
__device__ signed char g_w8[NTAPS * 2 * K_OUT * C_IN];

__device__ __forceinline__ uint32_t smem_u32(const void* p) {
    uint32_t a;
    asm("{ .reg .u64 t; cvta.to.shared.u64 t, %1; cvt.u32.u64 %0, t; }"
        : "=r"(a) : "l"(p));
    return a;
}
#define CP16(dst, src) \
    asm volatile("cp.async.cg.shared.global [%0], [%1], 16;" \
                 :: "r"(dst), "l"(src) : "memory")
#define CP_COMMIT() asm volatile("cp.async.commit_group;" ::: "memory")
#define CP_WAIT1()  asm volatile("cp.async.wait_group 1;" ::: "memory")
#define CP_WAIT0()  asm volatile("cp.async.wait_group 0;" ::: "memory")

/* =============== prep 1: clamp+trunc fp32 NCHW -> int8 NHWC =============== */
__global__ void qtrans_kernel(const float* __restrict__ x) {
    __shared__ signed char tile[C_IN * 57];
    int np = blockIdx.x;                       /* n*56 + p */
    int n = np / H_IN, p = np - n * H_IN;
    const float* src = x + (size_t)n * C_IN * H_IN * W_IN + p * W_IN;
    for (int idx = threadIdx.x; idx < C_IN * W_IN; idx += 256) {
        int c = idx / W_IN, q = idx - c * W_IN;
        float v = src[c * (H_IN * W_IN) + q];
        v = fminf(fmaxf(v, -128.f), 127.f);
        tile[c * 57 + q] = (signed char)v;     /* trunc toward zero */
    }
    __syncthreads();
    signed char* dst = g_x8 + (size_t)np * W_IN * C_IN;
    for (int idx = threadIdx.x; idx < W_IN * C_IN; idx += 256) {
        int q = idx >> 6, c = idx & 63;
        dst[idx] = tile[c * 57 + q];
    }
}

/* == prep 2: weights OIHW fp32 -> two int8 levels, w ~= w1*2^-9 + w2*2^-16 = */
__global__ void wtrans_kernel(const float* __restrict__ w) {
    int i = blockIdx.x * blockDim.x + threadIdx.x;
    if (i >= NTAPS * K_OUT * C_IN) return;
    int c   = i & 63;
    int ko  = (i >> 6) & 127;
    int tap = i >> 13;
    int r = tap / 3, s = tap - 3 * (tap / 3);
    float v = w[((ko * C_IN + c) * 3 + r) * 3 + s];
    int w1 = __float2int_rn(v * 512.f);
    w1 = max(-127, min(127, w1));
    float res = v - (float)w1 * (1.f / 512.f);
    int w2 = __float2int_rn(res * 65536.f);
    w2 = max(-127, min(127, w2));
    g_w8[(tap * 2 + 0) * (K_OUT * C_IN) + ko * C_IN + c] = (signed char)w1;
    g_w8[(tap * 2 + 1) * (K_OUT * C_IN) + ko * C_IN + c] = (signed char)w2;
}

/* ============== main: int8 IMMA implicit-GEMM, cp.async pipelined ========= */
extern __shared__ unsigned char smem_raw[];

__global__ void __launch_bounds__(512, 1)
conv_kernel(const float* __restrict__ bias, float* __restrict__ out) {
    unsigned char* sm = smem_raw;
    int*   in_byte = (int*)sm;                 /* [128] */
    int*   out_off = (int*)(sm + 512);         /* [128] */
    float* bias_s  = (float*)(sm + 1024);      /* [128] */
    const uint32_t smem_base = smem_u32(sm);
    const int tid = threadIdx.x;

    if (tid < 128) {
        int gm  = blockIdx.x * M_TILE + tid;
        int n   = gm / PQ;
        int rem = gm - n * PQ;
        int p   = rem / W_OUT;
        int q   = rem - p * W_OUT;
        in_byte[tid] = ((n * H_IN + p) * W_IN + q) * C_IN;
        out_off[tid] = n * (K_OUT * PQ) + rem;
        bias_s[tid]  = bias[tid];
    }
    __syncthreads();

    const int m_ld = tid >> 2, seg = tid & 3;
    const int my_in = in_byte[m_ld] + seg * 16;

    auto load_stage = [&](int tap, int st) {
        int r = tap / 3, s = tap - 3 * (tap / 3);
        /* A: 128 px x 64 ch, one 16B cp.async per thread */
        const signed char* asrc = g_x8 + (r * W_IN + s) * C_IN + my_in;
        uint32_t adst = smem_base + OFF_A + st * STAGE + m_ld * LDA + seg * 16;
        CP16(adst, asrc);
        /* B: 2 levels x 128 ko x 64 ch, two 16B per thread */
        const signed char* bsrc = g_w8 + tap * (2 * K_OUT * C_IN) + tid * 16;
        uint32_t bdst = smem_base + OFF_A + st * STAGE + A_BYTES
                      + m_ld * LDB + seg * 16;
        CP16(bdst, bsrc);
        CP16(bdst + 128 * LDB, bsrc + K_OUT * C_IN);
    };

    const int w  = tid >> 5;
    const int m0 = (w >> 2) * 32;      /* 4 warps along M */
    const int n0 = (w & 3) * 32;       /* 4 warps along N */

    wmma::fragment<wmma::accumulator, 16, 16, 16, int> acc1[2][2], acc2[2][2];
#pragma unroll
    for (int i = 0; i < 2; i++)
#pragma unroll
        for (int j = 0; j < 2; j++) {
            wmma::fill_fragment(acc1[i][j], 0);
            wmma::fill_fragment(acc2[i][j], 0);
        }

    load_stage(0, 0);
    CP_COMMIT();

    for (int t = 0; t < NTAPS; t++) {
        int st = t & 1;
        if (t < NTAPS - 1) {
            load_stage(t + 1, st ^ 1);
            CP_COMMIT();
            CP_WAIT1();
        } else {
            CP_WAIT0();
        }
        __syncthreads();

        const signed char* As = (const signed char*)(sm + OFF_A + st * STAGE);
        const signed char* Bs = As + A_BYTES;
#pragma unroll
        for (int kk = 0; kk < 4; kk++) {
            wmma::fragment<wmma::matrix_a, 16, 16, 16, signed char,
                           wmma::row_major> a[2];
            wmma::fragment<wmma::matrix_b, 16, 16, 16, signed char,
                           wmma::col_major> b1[2], b2[2];
#pragma unroll
            for (int i = 0; i < 2; i++)
                wmma::load_matrix_sync(a[i], As + (m0 + i * 16) * LDA + kk * 16,
                                       LDA);
#pragma unroll
            for (int j = 0; j < 2; j++) {
                wmma::load_matrix_sync(b1[j], Bs + (n0 + j * 16) * LDB + kk * 16,
                                       LDB);
                wmma::load_matrix_sync(b2[j],
                                       Bs + 128 * LDB + (n0 + j * 16) * LDB + kk * 16,
                                       LDB);
            }
#pragma unroll
            for (int i = 0; i < 2; i++)
#pragma unroll
                for (int j = 0; j < 2; j++) {
                    wmma::mma_sync(acc1[i][j], a[i], b1[j], acc1[i][j]);
                    wmma::mma_sync(acc2[i][j], a[i], b2[j], acc2[i][j]);
                }
        }
        __syncthreads();
    }

    /* ---- epilogue: combine levels in fp32, stage [ko][m], coalesced store - */
    float* Os = (float*)(sm + OFF_A);
#pragma unroll
    for (int i = 0; i < 2; i++)
#pragma unroll
        for (int j = 0; j < 2; j++) {
            wmma::fragment<wmma::accumulator, 16, 16, 16, float> f;
#pragma unroll
            for (int e = 0; e < f.num_elements; e++)
                f.x[e] = fmaf((float)acc1[i][j].x[e], 1.f / 512.f,
                              (float)acc2[i][j].x[e] * (1.f / 65536.f));
            wmma::store_matrix_sync(Os + (n0 + j * 16) * LDO + (m0 + i * 16),
                                    f, LDO, wmma::mem_col_major);
        }
    __syncthreads();

    for (int i = tid; i < M_TILE * K_OUT; i += 512) {
        int ko = i >> 7;
        int m  = i & 127;
        out[out_off[m] + ko * PQ] = Os[ko * LDO + m] + bias_s[ko];
    }
}

/* ========================================================================= */
extern "C" void kernel_launch(void* const* d_in, const int* in_sizes, int n_in,
                              void* d_out, int out_size) {
    const float* x    = (const float*)d_in[0];
    const float* w    = (const float*)d_in[1];
    const float* bias = (const float*)d_in[2];
    float* out = (float*)d_out;

    cudaFuncSetAttribute(conv_kernel,
                         cudaFuncAttributeMaxDynamicSharedMemorySize,
                         SMEM_TOTAL);

    qtrans_kernel<<<N_IMG * H_IN, 256>>>(x);
    wtrans_kernel<<<(NTAPS * K_OUT * C_IN + 255) / 256, 256>>>(w);
    conv_kernel<<<NCTA, 512, SMEM_TOTAL>>>(bias, out);
}

// round 6
// speedup vs baseline: 6.5098x; 6.5098x over previous
#include <cuda_runtime.h>
#include <cuda_fp16.h>
#include <mma.h>
#include <cstdint>

using namespace nvcuda;

#define N_IMG 64
#define C_IN  64
#define H_IN  56
#define W_IN  56
#define K_OUT 128
#define H_OUT 54
#define W_OUT 54
#define PQ    (H_OUT * W_OUT)          /* 2916   */
#define NPQ   (N_IMG * PQ)             /* 186624 */

#define M_TILE 128
#define NCTA   (NPQ / M_TILE)          /* 1458 exact */
#define NTAPS  9

#define LDA_H 72                        /* A row stride in halves (144 B)  */
#define LDB_H 136                       /* B row stride in halves (272 B)  */
#define LDO   132                       /* epilogue staging stride, floats */

#define A_BYTES (128 * LDA_H * 2)       /* 18432 */
#define B_BYTES (64 * LDB_H * 2)        /* 17408 */
#define STAGE   (A_BYTES + B_BYTES)     /* 35840 */
#define OFF_STG 2048
#define SMEM_TOTAL (OFF_STG + 2 * STAGE)   /* 73728 */

/* x as NHWC fp16 (int8-valued, exact; 51MB -> L2-resident working set) */
__device__ __half g_xh[(size_t)N_IMG * H_IN * W_IN * C_IN];
/* weights [tap][c][ko] fp16 */
__device__ __half g_wh[NTAPS * C_IN * K_OUT];

__device__ __forceinline__ uint32_t smem_u32(const void* p) {
    uint32_t a;
    asm("{ .reg .u64 t; cvta.to.shared.u64 t, %1; cvt.u32.u64 %0, t; }"
        : "=r"(a) : "l"(p));
    return a;
}
#define CP16(dst, src) \
    asm volatile("cp.async.cg.shared.global [%0], [%1], 16;" \
                 :: "r"(dst), "l"(src) : "memory")
#define CP_COMMIT() asm volatile("cp.async.commit_group;" ::: "memory")
#define CP_WAIT1()  asm volatile("cp.async.wait_group 1;" ::: "memory")
#define CP_WAIT0()  asm volatile("cp.async.wait_group 0;" ::: "memory")

/* =============== prep 1: clamp+trunc fp32 NCHW -> fp16 NHWC =============== */
__global__ void qtrans_kernel(const float* __restrict__ x) {
    __shared__ __half tile[C_IN * 57];
    int np = blockIdx.x;                       /* n*56 + p */
    int n = np / H_IN, p = np - n * H_IN;
    const float* src = x + (size_t)n * C_IN * H_IN * W_IN + p * W_IN;
    for (int idx = threadIdx.x; idx < C_IN * W_IN; idx += 256) {
        int c = idx / W_IN, q = idx - c * W_IN;
        float v = src[c * (H_IN * W_IN) + q];
        v = fminf(fmaxf(v, -128.f), 127.f);
        tile[c * 57 + q] = __float2half_rn((float)(int)v);  /* trunc, exact */
    }
    __syncthreads();
    __half* dst = g_xh + (size_t)np * W_IN * C_IN;
    for (int idx = threadIdx.x; idx < W_IN * C_IN; idx += 256) {
        int q = idx >> 6, c = idx & 63;
        dst[idx] = tile[c * 57 + q];
    }
}

/* ============ prep 2: weights OIHW fp32 -> [tap][c][ko] fp16 ============== */
__global__ void wtrans_kernel(const float* __restrict__ w) {
    int i = blockIdx.x * blockDim.x + threadIdx.x;
    if (i >= NTAPS * K_OUT * C_IN) return;
    int ko  = i & 127;
    int c   = (i >> 7) & 63;
    int tap = i >> 13;
    int r = tap / 3, s = tap - 3 * (tap / 3);
    g_wh[i] = __float2half_rn(w[((ko * C_IN + c) * 3 + r) * 3 + s]);
}

/* ============== main: fp16 HMMA implicit-GEMM, cp.async pipelined ========= */
extern __shared__ unsigned char smem_raw[];

__global__ void __launch_bounds__(256, 2)
conv_kernel(const float* __restrict__ bias, float* __restrict__ out) {
    unsigned char* sm = smem_raw;
    int*   in_off  = (int*)sm;                 /* [128] NHWC element offset */
    int*   out_off = (int*)(sm + 512);         /* [128] */
    float* bias_s  = (float*)(sm + 1024);      /* [128] */
    const uint32_t smem_base = smem_u32(sm);
    const int tid = threadIdx.x;

    if (tid < 128) {
        int gm  = blockIdx.x * M_TILE + tid;
        int n   = gm / PQ;
        int rem = gm - n * PQ;
        int p   = rem / W_OUT;
        int q   = rem - p * W_OUT;
        in_off[tid]  = ((n * H_IN + p) * W_IN + q) * C_IN;
        out_off[tid] = n * (K_OUT * PQ) + rem;
        bias_s[tid]  = bias[tid];
    }
    __syncthreads();

    /* per-thread cp.async assignments (4 A-chunks + 4 B-chunks of 16B) */
    auto load_stage = [&](int tap, int st) {
        uint32_t base = smem_base + OFF_STG + st * STAGE;
        int r = tap / 3, s = tap - 3 * (tap / 3);
        int tap_e = (r * W_IN + s) * C_IN;           /* element offset */
        const unsigned char* xb = (const unsigned char*)g_xh;
#pragma unroll
        for (int j = 0; j < 4; j++) {
            int i  = tid + j * 256;                  /* 1024 chunks */
            int px = i >> 3, seg = i & 7;            /* 8 x 16B per pixel */
            const void* src = xb + (size_t)(in_off[px] + tap_e) * 2 + seg * 16;
            CP16(base + px * (LDA_H * 2) + seg * 16, src);
        }
        const unsigned char* wb =
            (const unsigned char*)(g_wh + tap * (C_IN * K_OUT));
#pragma unroll
        for (int j = 0; j < 4; j++) {
            int i = tid + j * 256;                   /* 1024 chunks */
            int k = i >> 4, c16 = i & 15;            /* 16 x 16B per k-row */
            CP16(base + A_BYTES + k * (LDB_H * 2) + c16 * 16,
                 wb + k * 256 + c16 * 16);
        }
    };

    const int warp_m = (tid >> 5) & 1;     /* 2 warps along M (64 rows) */
    const int warp_n = (tid >> 6);         /* 4 warps along N (32 cols) */
    const int m0 = warp_m * 64;
    const int n0 = warp_n * 32;

    wmma::fragment<wmma::accumulator, 16, 16, 16, float> acc[4][2];
#pragma unroll
    for (int i = 0; i < 4; i++)
#pragma unroll
        for (int j = 0; j < 2; j++)
            wmma::fill_fragment(acc[i][j], 0.0f);

    load_stage(0, 0);
    CP_COMMIT();

    for (int t = 0; t < NTAPS; t++) {
        int st = t & 1;
        if (t < NTAPS - 1) {
            load_stage(t + 1, st ^ 1);
            CP_COMMIT();
            CP_WAIT1();
        } else {
            CP_WAIT0();
        }
        __syncthreads();

        const __half* As = (const __half*)(sm + OFF_STG + st * STAGE);
        const __half* Bs = As + A_BYTES / 2;
#pragma unroll
        for (int kk = 0; kk < 4; kk++) {
            wmma::fragment<wmma::matrix_a, 16, 16, 16, __half,
                           wmma::row_major> a[4];
            wmma::fragment<wmma::matrix_b, 16, 16, 16, __half,
                           wmma::row_major> b[2];
#pragma unroll
            for (int i = 0; i < 4; i++)
                wmma::load_matrix_sync(a[i],
                    As + (m0 + i * 16) * LDA_H + kk * 16, LDA_H);
#pragma unroll
            for (int j = 0; j < 2; j++)
                wmma::load_matrix_sync(b[j],
                    Bs + (kk * 16) * LDB_H + n0 + j * 16, LDB_H);
#pragma unroll
            for (int i = 0; i < 4; i++)
#pragma unroll
                for (int j = 0; j < 2; j++)
                    wmma::mma_sync(acc[i][j], a[i], b[j], acc[i][j]);
        }
        __syncthreads();   /* all warps done with stage st before reuse */
    }

    /* ---- epilogue: stage [ko][m] fp32 in smem, coalesced NCHW stores ----- */
    float* Os = (float*)(sm + OFF_STG);
#pragma unroll
    for (int i = 0; i < 4; i++)
#pragma unroll
        for (int j = 0; j < 2; j++)
            wmma::store_matrix_sync(Os + (n0 + j * 16) * LDO + (m0 + i * 16),
                                    acc[i][j], LDO, wmma::mem_col_major);
    __syncthreads();

#pragma unroll
    for (int j = 0; j < 64; j++) {
        int i  = tid + j * 256;
        int ko = i >> 7;
        int m  = i & 127;
        out[out_off[m] + ko * PQ] = Os[ko * LDO + m] + bias_s[ko];
    }
}

/* ========================================================================= */
extern "C" void kernel_launch(void* const* d_in, const int* in_sizes, int n_in,
                              void* d_out, int out_size) {
    const float* x    = (const float*)d_in[0];
    const float* w    = (const float*)d_in[1];
    const float* bias = (const float*)d_in[2];
    float* out = (float*)d_out;

    cudaFuncSetAttribute(conv_kernel,
                         cudaFuncAttributeMaxDynamicSharedMemorySize,
                         SMEM_TOTAL);

    qtrans_kernel<<<N_IMG * H_IN, 256>>>(x);
    wtrans_kernel<<<(NTAPS * K_OUT * C_IN + 255) / 256, 256>>>(w);
    conv_kernel<<<NCTA, 256, SMEM_TOTAL>>>(bias, out);
}

// round 7
// speedup vs baseline: 6.8964x; 1.0594x over previous
#include <cuda_runtime.h>
#include <cuda_fp16.h>
#include <mma.h>
#include <cstdint>

using namespace nvcuda;

#define N_IMG 64
#define C_IN  64
#define H_IN  56
#define W_IN  56
#define HW_IN (H_IN * W_IN)
#define K_OUT 128
#define H_OUT 54
#define W_OUT 54
#define PQ    (H_OUT * W_OUT)          /* 2916   */
#define NPQ   (N_IMG * PQ)             /* 186624 */

#define M_TILE 128
#define NCTA   (NPQ / M_TILE)          /* 1458 exact */
#define NTAPS  9

#define LDA_H 72                        /* A row stride in halves (144 B)  */
#define LDB_H 136                       /* B row stride in halves (272 B)  */
#define LDO   132                       /* epilogue staging stride, floats */

#define A_BYTES (128 * LDA_H * 2)       /* 18432 */
#define B_BYTES (64 * LDB_H * 2)        /* 17408 */
#define STAGE   (A_BYTES + B_BYTES)     /* 35840 */
#define OFF_STG 2048
#define SMEM_TOTAL (OFF_STG + 2 * STAGE)   /* 73728 */

/* x as NHWC fp16 (int8-valued, exact) */
__device__ __half g_xh[(size_t)N_IMG * H_IN * W_IN * C_IN];
/* weights [tap][c][ko] fp16 */
__device__ __half g_wh[NTAPS * C_IN * K_OUT];

__device__ __forceinline__ uint32_t smem_u32(const void* p) {
    uint32_t a;
    asm("{ .reg .u64 t; cvta.to.shared.u64 t, %1; cvt.u32.u64 %0, t; }"
        : "=r"(a) : "l"(p));
    return a;
}
#define CP16(dst, src) \
    asm volatile("cp.async.cg.shared.global [%0], [%1], 16;" \
                 :: "r"(dst), "l"(src) : "memory")
#define CP_COMMIT() asm volatile("cp.async.commit_group;" ::: "memory")
#define CP_WAIT0()  asm volatile("cp.async.wait_group 0;" ::: "memory")

/* =============== prep 1: clamp+trunc fp32 NCHW -> fp16 NHWC =============== */
__global__ void __launch_bounds__(256) qtrans_kernel(const float* __restrict__ x) {
    __shared__ __half tile[C_IN * 60];         /* stride 60: 8B-aligned rows */
    int np = blockIdx.x;                       /* n*56 + p */
    int n = np / H_IN, p = np - n * H_IN;
    const float* src = x + (size_t)n * C_IN * HW_IN + p * W_IN;

    /* 896 float4 chunks: c in [0,64), qg in [0,14) */
    for (int i = threadIdx.x; i < 896; i += 256) {
        int c = i / 14, qg = i - c * 14;
        float4 v = *(const float4*)(src + c * HW_IN + qg * 4);
        union { __half h[4]; uint2 u; } pk;
        pk.h[0] = __float2half_rn((float)(int)fminf(fmaxf(v.x, -128.f), 127.f));
        pk.h[1] = __float2half_rn((float)(int)fminf(fmaxf(v.y, -128.f), 127.f));
        pk.h[2] = __float2half_rn((float)(int)fminf(fmaxf(v.z, -128.f), 127.f));
        pk.h[3] = __float2half_rn((float)(int)fminf(fmaxf(v.w, -128.f), 127.f));
        *(uint2*)&tile[c * 60 + qg * 4] = pk.u;
    }
    __syncthreads();

    /* 448 uint4 stores: q in [0,56), c8 in [0,8) */
    uint4* dst = (uint4*)(g_xh + (size_t)np * (W_IN * C_IN));
    for (int i = threadIdx.x; i < 448; i += 256) {
        int q = i >> 3, c8 = i & 7;
        union { __half h[8]; uint4 u; } pk;
#pragma unroll
        for (int j = 0; j < 8; j++) pk.h[j] = tile[(c8 * 8 + j) * 60 + q];
        dst[q * 8 + c8] = pk.u;
    }
}

/* ============ prep 2: weights OIHW fp32 -> [tap][c][ko] fp16 ============== */
__global__ void wtrans_kernel(const float* __restrict__ w) {
    int i = blockIdx.x * blockDim.x + threadIdx.x;
    if (i >= NTAPS * K_OUT * C_IN) return;
    int ko  = i & 127;
    int c   = (i >> 7) & 63;
    int tap = i >> 13;
    int r = tap / 3, s = tap - 3 * (tap / 3);
    g_wh[i] = __float2half_rn(w[((ko * C_IN + c) * 3 + r) * 3 + s]);
}

/* ====== main: fp16 HMMA implicit-GEMM, single-sync cp.async pipeline ====== */
extern __shared__ unsigned char smem_raw[];

__global__ void __launch_bounds__(256, 2)
conv_kernel(const float* __restrict__ bias, float* __restrict__ out) {
    unsigned char* sm = smem_raw;
    int*   in_off  = (int*)sm;                 /* [128] NHWC element offset */
    int*   out_off = (int*)(sm + 512);         /* [128] */
    float* bias_s  = (float*)(sm + 1024);      /* [128] */
    const uint32_t smem_base = smem_u32(sm);
    const int tid = threadIdx.x;

    if (tid < 128) {
        int gm  = blockIdx.x * M_TILE + tid;
        int n   = gm / PQ;
        int rem = gm - n * PQ;
        int p   = rem / W_OUT;
        int q   = rem - p * W_OUT;
        in_off[tid]  = ((n * H_IN + p) * W_IN + q) * C_IN;
        out_off[tid] = n * (K_OUT * PQ) + rem;
        bias_s[tid]  = bias[tid];
    }
    __syncthreads();

    /* hoist per-thread A offsets (4 pixels per thread, fixed seg) */
    const int seg = tid & 7;                   /* 8 x 16B per pixel row */
    const int px0 = tid >> 3;
    int a_off[4];
#pragma unroll
    for (int j = 0; j < 4; j++) a_off[j] = in_off[px0 + 32 * j];

    const int bk  = tid >> 4;                  /* B: k-row base             */
    const int bc  = tid & 15;                  /* B: 16B chunk within k-row */

    auto load_stage = [&](int tap, int st) {
        uint32_t base = smem_base + OFF_STG + st * STAGE;
        int r = tap / 3, s = tap - 3 * (tap / 3);
        int tap_e = (r * W_IN + s) * C_IN;
        const unsigned char* xb = (const unsigned char*)g_xh;
#pragma unroll
        for (int j = 0; j < 4; j++) {
            int px = px0 + 32 * j;
            const void* src = xb + (size_t)(a_off[j] + tap_e) * 2 + seg * 16;
            CP16(base + px * (LDA_H * 2) + seg * 16, src);
        }
        const unsigned char* wb =
            (const unsigned char*)(g_wh + tap * (C_IN * K_OUT));
#pragma unroll
        for (int j = 0; j < 4; j++) {
            int k = bk + 16 * j;
            CP16(base + A_BYTES + k * (LDB_H * 2) + bc * 16,
                 wb + k * 256 + bc * 16);
        }
    };

    const int warp_m = (tid >> 5) & 1;
    const int warp_n = (tid >> 6);
    const int m0 = warp_m * 64;
    const int n0 = warp_n * 32;

    wmma::fragment<wmma::accumulator, 16, 16, 16, float> acc[4][2];
#pragma unroll
    for (int i = 0; i < 4; i++)
#pragma unroll
        for (int j = 0; j < 2; j++)
            wmma::fill_fragment(acc[i][j], 0.0f);

    load_stage(0, 0);
    CP_COMMIT();

    for (int t = 0; t < NTAPS; t++) {
        int st = t & 1;
        CP_WAIT0();                 /* stage st data landed                  */
        __syncthreads();            /* + all warps done with stage st^1 MMA */
        if (t < NTAPS - 1) {        /* prefetch t+1 overlaps MMA(t)          */
            load_stage(t + 1, st ^ 1);
            CP_COMMIT();
        }

        const __half* As = (const __half*)(sm + OFF_STG + st * STAGE);
        const __half* Bs = As + A_BYTES / 2;
#pragma unroll
        for (int kk = 0; kk < 4; kk++) {
            wmma::fragment<wmma::matrix_a, 16, 16, 16, __half,
                           wmma::row_major> a[4];
            wmma::fragment<wmma::matrix_b, 16, 16, 16, __half,
                           wmma::row_major> b[2];
#pragma unroll
            for (int i = 0; i < 4; i++)
                wmma::load_matrix_sync(a[i],
                    As + (m0 + i * 16) * LDA_H + kk * 16, LDA_H);
#pragma unroll
            for (int j = 0; j < 2; j++)
                wmma::load_matrix_sync(b[j],
                    Bs + (kk * 16) * LDB_H + n0 + j * 16, LDB_H);
#pragma unroll
            for (int i = 0; i < 4; i++)
#pragma unroll
                for (int j = 0; j < 2; j++)
                    wmma::mma_sync(acc[i][j], a[i], b[j], acc[i][j]);
        }
    }
    __syncthreads();   /* all warps done reading smem before Os overwrite */

    /* ---- epilogue: stage [ko][m] fp32 in smem, coalesced NCHW stores ----- */
    float* Os = (float*)(sm + OFF_STG);
#pragma unroll
    for (int i = 0; i < 4; i++)
#pragma unroll
        for (int j = 0; j < 2; j++)
            wmma::store_matrix_sync(Os + (n0 + j * 16) * LDO + (m0 + i * 16),
                                    acc[i][j], LDO, wmma::mem_col_major);
    __syncthreads();

#pragma unroll
    for (int j = 0; j < 64; j++) {
        int i  = tid + j * 256;
        int ko = i >> 7;
        int m  = i & 127;
        out[out_off[m] + ko * PQ] = Os[ko * LDO + m] + bias_s[ko];
    }
}

/* ========================================================================= */
extern "C" void kernel_launch(void* const* d_in, const int* in_sizes, int n_in,
                              void* d_out, int out_size) {
    const float* x    = (const float*)d_in[0];
    const float* w    = (const float*)d_in[1];
    const float* bias = (const float*)d_in[2];
    float* out = (float*)d_out;

    cudaFuncSetAttribute(conv_kernel,
                         cudaFuncAttributeMaxDynamicSharedMemorySize,
                         SMEM_TOTAL);

    qtrans_kernel<<<N_IMG * H_IN, 256>>>(x);
    wtrans_kernel<<<(NTAPS * K_OUT * C_IN + 255) / 256, 256>>>(w);
    conv_kernel<<<NCTA, 256, SMEM_TOTAL>>>(bias, out);
}